// round 2
// baseline (speedup 1.0000x reference)
#include <cuda_runtime.h>

#define BB 8
#define NN 1024
#define HH 32
#define BN (BB*NN)

typedef unsigned long long u64;

// Scratch: per-node first-layer partials u[n][h] = rho*W1[0][h] + V*W1[1][h] + 0.5*b1[h]
__device__ float g_u[BN * HH];

__device__ __forceinline__ float lrelu(float v) { return fmaxf(v, 0.01f * v); }

__device__ __forceinline__ u64 pack2(float a, float b) {
    u64 r; asm("mov.b64 %0, {%1,%2};" : "=l"(r) : "f"(a), "f"(b)); return r;
}
__device__ __forceinline__ void unpack2(u64 v, float &a, float &b) {
    asm("mov.b64 {%0,%1}, %2;" : "=f"(a), "=f"(b) : "l"(v));
}
// Packed dual-FMA: acc.{lo,hi} += w.{lo,hi} * a.{lo,hi}
__device__ __forceinline__ void ffma2(u64 &acc, u64 w, u64 a) {
    asm("fma.rn.f32x2 %0, %1, %2, %0;" : "+l"(acc) : "l"(w), "l"(a));
}

// ---------------------------------------------------------------------------
// Kernel 1: per-node layer-1 partials.
// ---------------------------------------------------------------------------
__global__ void precompute_u(const float* __restrict__ x,
                             const float* __restrict__ Wm1,
                             const float* __restrict__ bm1) {
    int idx = blockIdx.x * blockDim.x + threadIdx.x;   // [0, BN*HH)
    int node = idx >> 5;
    int h = idx & 31;
    float rho = x[node * 2 + 0];
    float V   = x[node * 2 + 1];
    g_u[idx] = rho * Wm1[h] + V * Wm1[HH + h] + 0.5f * bm1[h];
}

// One layer-2 k-step: a2 = (h1[K],h1[K]); 16 packed FMAs against W2 row K.
// All accumulators are NAMED variables -> guaranteed register residency.
#define L2STEP(K) do {                                                        \
    u64 a2 = pack2(h1[K], h1[K]);                                             \
    ulonglong2 w0 = wr[(K)*8+0], w1 = wr[(K)*8+1],                            \
               w2 = wr[(K)*8+2], w3 = wr[(K)*8+3];                            \
    ffma2(c0,  w0.x, a2); ffma2(c1,  w0.y, a2);                               \
    ffma2(c2,  w1.x, a2); ffma2(c3,  w1.y, a2);                               \
    ffma2(c4,  w2.x, a2); ffma2(c5,  w2.y, a2);                               \
    ffma2(c6,  w3.x, a2); ffma2(c7,  w3.y, a2);                               \
    ulonglong2 w4 = wr[(K)*8+4], w5 = wr[(K)*8+5],                            \
               w6 = wr[(K)*8+6], w7 = wr[(K)*8+7];                            \
    ffma2(c8,  w4.x, a2); ffma2(c9,  w4.y, a2);                               \
    ffma2(c10, w5.x, a2); ffma2(c11, w5.y, a2);                               \
    ffma2(c12, w6.x, a2); ffma2(c13, w6.y, a2);                               \
    ffma2(c14, w7.x, a2); ffma2(c15, w7.y, a2);                               \
} while (0)

// ---------------------------------------------------------------------------
// Kernel 2: fused pair-MLP + A-weighted reduction + node MLP.
// One block per (b, i). 256 threads; each thread handles 4 j values.
// ---------------------------------------------------------------------------
__global__ __launch_bounds__(256) void mpnn_main(
    const float* __restrict__ x,   const float* __restrict__ A,
    const float* __restrict__ Wm2, const float* __restrict__ bm2,
    const float* __restrict__ Wm3, const float* __restrict__ bm3,
    const float* __restrict__ Wx1, const float* __restrict__ bx1,
    const float* __restrict__ Wx2, const float* __restrict__ bx2,
    const float* __restrict__ Wx3, const float* __restrict__ bx3,
    float* __restrict__ out)
{
    __shared__ float4 W2s[HH * 8];     // Wm2 row-major [k][l], 1024 floats
    __shared__ float  W3s[HH];
    __shared__ float  b2s[HH];
    __shared__ float  uis[HH];
    __shared__ float  red[256];
    __shared__ float  hsh[HH];

    const int bi  = blockIdx.x;        // b*N + i
    const int i   = bi & (NN - 1);
    const int tid = threadIdx.x;

    W2s[tid] = reinterpret_cast<const float4*>(Wm2)[tid];  // 256 float4 = 1024 floats
    if (tid < HH) {
        W3s[tid] = Wm3[tid];
        b2s[tid] = bm2[tid];
        uis[tid] = g_u[bi * HH + tid];
    }
    __syncthreads();

    const ulonglong2* wr = reinterpret_cast<const ulonglong2*>(W2s);
    const u64*  b2p = reinterpret_cast<const u64*>(b2s);
    const float* uB   = g_u + (bi & ~(NN - 1)) * HH;  // batch base of u
    const float* Arow = A + (long)i * NN;
    const float  bm3v = bm3[0];

    float acc = 0.0f;

    #pragma unroll 1
    for (int j = tid; j < NN; j += 256) {
        // h1 = lrelu(u_i + u_j)   (b1 split half into each u)
        float h1[HH];
        const float4* up = reinterpret_cast<const float4*>(uB + j * HH);
        #pragma unroll
        for (int m = 0; m < 8; ++m) {
            float4 t = up[m];
            h1[4*m+0] = lrelu(uis[4*m+0] + t.x);
            h1[4*m+1] = lrelu(uis[4*m+1] + t.y);
            h1[4*m+2] = lrelu(uis[4*m+2] + t.z);
            h1[4*m+3] = lrelu(uis[4*m+3] + t.w);
        }

        // h2 = bm2 + W2^T h1 : 16 named packed accumulators
        u64 c0  = b2p[0],  c1  = b2p[1],  c2  = b2p[2],  c3  = b2p[3];
        u64 c4  = b2p[4],  c5  = b2p[5],  c6  = b2p[6],  c7  = b2p[7];
        u64 c8  = b2p[8],  c9  = b2p[9],  c10 = b2p[10], c11 = b2p[11];
        u64 c12 = b2p[12], c13 = b2p[13], c14 = b2p[14], c15 = b2p[15];

        L2STEP(0);  L2STEP(1);  L2STEP(2);  L2STEP(3);
        L2STEP(4);  L2STEP(5);  L2STEP(6);  L2STEP(7);
        L2STEP(8);  L2STEP(9);  L2STEP(10); L2STEP(11);
        L2STEP(12); L2STEP(13); L2STEP(14); L2STEP(15);
        L2STEP(16); L2STEP(17); L2STEP(18); L2STEP(19);
        L2STEP(20); L2STEP(21); L2STEP(22); L2STEP(23);
        L2STEP(24); L2STEP(25); L2STEP(26); L2STEP(27);
        L2STEP(28); L2STEP(29); L2STEP(30); L2STEP(31);

        // me = tanh(W3 . lrelu(h2) + b3)
        float s = 0.0f;
        {
            float a, b;
            unpack2(c0,  a, b); s += lrelu(a)*W3s[0]  + lrelu(b)*W3s[1];
            unpack2(c1,  a, b); s += lrelu(a)*W3s[2]  + lrelu(b)*W3s[3];
            unpack2(c2,  a, b); s += lrelu(a)*W3s[4]  + lrelu(b)*W3s[5];
            unpack2(c3,  a, b); s += lrelu(a)*W3s[6]  + lrelu(b)*W3s[7];
            unpack2(c4,  a, b); s += lrelu(a)*W3s[8]  + lrelu(b)*W3s[9];
            unpack2(c5,  a, b); s += lrelu(a)*W3s[10] + lrelu(b)*W3s[11];
            unpack2(c6,  a, b); s += lrelu(a)*W3s[12] + lrelu(b)*W3s[13];
            unpack2(c7,  a, b); s += lrelu(a)*W3s[14] + lrelu(b)*W3s[15];
            unpack2(c8,  a, b); s += lrelu(a)*W3s[16] + lrelu(b)*W3s[17];
            unpack2(c9,  a, b); s += lrelu(a)*W3s[18] + lrelu(b)*W3s[19];
            unpack2(c10, a, b); s += lrelu(a)*W3s[20] + lrelu(b)*W3s[21];
            unpack2(c11, a, b); s += lrelu(a)*W3s[22] + lrelu(b)*W3s[23];
            unpack2(c12, a, b); s += lrelu(a)*W3s[24] + lrelu(b)*W3s[25];
            unpack2(c13, a, b); s += lrelu(a)*W3s[26] + lrelu(b)*W3s[27];
            unpack2(c14, a, b); s += lrelu(a)*W3s[28] + lrelu(b)*W3s[29];
            unpack2(c15, a, b); s += lrelu(a)*W3s[30] + lrelu(b)*W3s[31];
        }
        float me = tanhf(s + bm3v);
        acc += Arow[j] * me;           // coalesced A read
    }

    // Block reduction of A-weighted message sum.
    red[tid] = acc;
    __syncthreads();
    #pragma unroll
    for (int s2 = 128; s2 > 0; s2 >>= 1) {
        if (tid < s2) red[tid] += red[tid + s2];
        __syncthreads();
    }

    // Node MLP: x2 = (rho_i, msg_sum) -> 32 -> 32 -> 1 (warp 0, lane = hidden unit)
    if (tid < HH) {
        const float msum = red[0];
        const float rho  = x[bi * 2 + 0];
        const int   l    = tid;

        float h1b = lrelu(rho * Wx1[l] + msum * Wx1[HH + l] + bx1[l]);
        hsh[l] = h1b;
        __syncwarp();

        float h2b = bx2[l];
        #pragma unroll
        for (int k = 0; k < HH; ++k) h2b += Wx2[k * HH + l] * hsh[k];

        float v = lrelu(h2b) * Wx3[l];
        #pragma unroll
        for (int off = 16; off; off >>= 1) v += __shfl_xor_sync(0xffffffffu, v, off);

        if (l == 0) out[bi] = tanhf(v + bx3[0]);
    }
}

// ---------------------------------------------------------------------------
extern "C" void kernel_launch(void* const* d_in, const int* in_sizes, int n_in,
                              void* d_out, int out_size) {
    const float* x   = (const float*)d_in[0];
    const float* A   = (const float*)d_in[1];
    const float* Wm1 = (const float*)d_in[2];
    const float* bm1 = (const float*)d_in[3];
    const float* Wm2 = (const float*)d_in[4];
    const float* bm2 = (const float*)d_in[5];
    const float* Wm3 = (const float*)d_in[6];
    const float* bm3 = (const float*)d_in[7];
    const float* Wx1 = (const float*)d_in[8];
    const float* bx1 = (const float*)d_in[9];
    const float* Wx2 = (const float*)d_in[10];
    const float* bx2 = (const float*)d_in[11];
    const float* Wx3 = (const float*)d_in[12];
    const float* bx3 = (const float*)d_in[13];
    float* out = (float*)d_out;

    precompute_u<<<(BN * HH) / 256, 256>>>(x, Wm1, bm1);
    mpnn_main<<<BN, 256>>>(x, A, Wm2, bm2, Wm3, bm3,
                           Wx1, bx1, Wx2, bx2, Wx3, bx3, out);
}